// round 2
// baseline (speedup 1.0000x reference)
#include <cuda_runtime.h>
#include <math.h>

#define NEGO 1024
#define NEDGE 49152
#define MM 6
#define HID 256
#define HH 128
#define NH 8
#define NM (NEGO*MM)
#define LNEPS 1e-5f

// ---------------- scratch (device globals; no allocation allowed) ----------------
__device__ float g_xn[NM*HID];          // LN output (both LN1 and LN2 reuse)
__device__ float g_q[NM*HID];           // q  (also reused as hmid2)
__device__ float g_hmid[NM*HID];        // FF mid
__device__ float g_qk[NM*NH*HH];        // folded q·Wk per node  [nm][h][c]
__device__ float g_sb[NM*NH];           // score bias  bk·q
__device__ float g_scores[NEDGE*MM*NH]; // raw scores
__device__ float g_mx[NM*NH];
__device__ float g_dn[NM*NH];
__device__ float g_ue[NM*NH*HH];        // alpha-weighted edge_feat sums
__device__ float g_un[NM*NH*HH];        // alpha-weighted node_feat sums
__device__ int   g_rowstart[NEGO+1];

// ---------------- segment offsets (batch is sorted) ----------------
__global__ void rowstart_kernel(const int* __restrict__ batch){
    int n = blockIdx.x*blockDim.x + threadIdx.x;
    if (n > NEGO) return;
    int lo = 0, hi = NEDGE;
    while (lo < hi){ int mid = (lo+hi)>>1; if (batch[mid] < n) lo = mid+1; else hi = mid; }
    g_rowstart[n] = lo;
}

// ---------------- LayerNorm: one warp per row of 256 ----------------
__global__ __launch_bounds__(256) void ln_kernel(
    const float* __restrict__ x, const float* __restrict__ w, const float* __restrict__ b)
{
    int warp = threadIdx.x >> 5, lane = threadIdx.x & 31;
    int row = blockIdx.x*8 + warp;
    const float* xr = x + (size_t)row*HID;
    float v[8]; float s = 0.f, s2 = 0.f;
    #pragma unroll
    for (int k=0;k<8;k++){ v[k] = xr[lane + k*32]; s += v[k]; s2 += v[k]*v[k]; }
    #pragma unroll
    for (int o=16;o>0;o>>=1){
        s  += __shfl_xor_sync(0xffffffffu, s,  o);
        s2 += __shfl_xor_sync(0xffffffffu, s2, o);
    }
    float mean = s*(1.f/HID);
    float var  = s2*(1.f/HID) - mean*mean;
    float rstd = rsqrtf(var + LNEPS);
    float* orow = g_xn + (size_t)row*HID;
    #pragma unroll
    for (int k=0;k<8;k++){ int c = lane + k*32; orow[c] = (v[k]-mean)*rstd*w[c] + b[c]; }
}

// ---------------- generic fp32 GEMM: [M,256] @ [256,256] + bias (+relu)(+resid) ----
// Asel: 0=g_xn 1=g_hmid 2=g_q ; Csel: 0=g_q 1=g_hmid 2=ego(+residual)
__global__ __launch_bounds__(256) void gemm_kernel(
    int Asel, const float* __restrict__ W, const float* __restrict__ bias,
    float* __restrict__ ego, int Csel, int relu)
{
    const float* A = (Asel==0) ? g_xn : (Asel==1) ? g_hmid : g_q;
    float*       C = (Csel==0) ? g_q  : (Csel==1) ? g_hmid : ego;
    __shared__ float As[16*68];
    __shared__ float Bs[16*68];
    int t = threadIdx.x;
    int m0 = blockIdx.x*64, n0 = blockIdx.y*64;
    int ty = t>>4, tx = t&15;
    float acc[4][4];
    #pragma unroll
    for (int i=0;i<4;i++)
        #pragma unroll
        for (int j=0;j<4;j++) acc[i][j] = 0.f;
    int ar = t>>2, akc = (t&3)*4;
    int br = t>>4, bc = (t&15)*4;
    const float* Ap = A + (size_t)(m0+ar)*256 + akc;
    const float* Wp = W + (size_t)br*256 + n0 + bc;
    for (int k0=0;k0<256;k0+=16){
        float4 a4 = *(const float4*)(Ap + k0);
        float4 b4 = *(const float4*)(Wp + (size_t)k0*256);
        As[(akc+0)*68+ar] = a4.x;
        As[(akc+1)*68+ar] = a4.y;
        As[(akc+2)*68+ar] = a4.z;
        As[(akc+3)*68+ar] = a4.w;
        *(float4*)&Bs[br*68+bc] = b4;
        __syncthreads();
        #pragma unroll
        for (int k=0;k<16;k++){
            float4 av = *(float4*)&As[k*68+ty*4];
            float4 bv = *(float4*)&Bs[k*68+tx*4];
            float aa[4] = {av.x,av.y,av.z,av.w};
            float bb[4] = {bv.x,bv.y,bv.z,bv.w};
            #pragma unroll
            for (int i=0;i<4;i++)
                #pragma unroll
                for (int j=0;j<4;j++) acc[i][j] += aa[i]*bb[j];
        }
        __syncthreads();
    }
    float4 bb4 = *(const float4*)&bias[n0+tx*4];
    float bi[4] = {bb4.x,bb4.y,bb4.z,bb4.w};
    #pragma unroll
    for (int i=0;i<4;i++){
        int row = m0 + ty*4 + i;
        float ov[4];
        #pragma unroll
        for (int j=0;j<4;j++){
            float v = acc[i][j] + bi[j];
            if (relu) v = fmaxf(v, 0.f);
            ov[j] = v;
        }
        float* cp = C + (size_t)row*256 + n0 + tx*4;
        if (Csel == 2){
            float4 r = *(const float4*)cp;
            ov[0]+=r.x; ov[1]+=r.y; ov[2]+=r.z; ov[3]+=r.w;
        }
        float4 o; o.x=ov[0]; o.y=ov[1]; o.z=ov[2]; o.w=ov[3];
        *(float4*)cp = o;
    }
}

// ---------------- fold Wk into q:  qk[nm,h,c] = sum_d Wk[c, h*32+d] * q[nm, h*32+d] ----
__global__ __launch_bounds__(256) void qkfold_kernel(
    const float* __restrict__ Wk, const float* __restrict__ bk)
{
    int nm = blockIdx.x, t = threadIdx.x;
    __shared__ float qv[256];
    qv[t] = g_q[(size_t)nm*256 + t];
    __syncthreads();
    #pragma unroll
    for (int j=0;j<4;j++){
        int o = t + j*256;
        int h = o>>7, c = o&127;
        const float* wrow = Wk + (size_t)c*256 + h*32;
        const float* qh = qv + h*32;
        float s = 0.f;
        #pragma unroll
        for (int d=0;d<32;d++) s += wrow[d]*qh[d];
        g_qk[(size_t)nm*1024 + o] = s;
    }
    if (t < 8){
        float s = 0.f;
        #pragma unroll
        for (int d=0;d<32;d++) s += bk[t*32+d]*qv[t*32+d];
        g_sb[nm*8+t] = s;
    }
}

// ---------------- scores + fused online segment-softmax stats ----------------
// block per (n,m); 256 threads = (32 edge slots) x (8 heads)
__global__ __launch_bounds__(256) void scores_kernel(const float* __restrict__ ef)
{
    int n = blockIdx.x, m = blockIdx.y;
    int nm = n*MM + m;
    int t = threadIdx.x;
    __shared__ float qs[8*132];
    __shared__ float sbs[8];
    __shared__ float efs[32*132];
    __shared__ float rm[256], rs[256];
    #pragma unroll
    for (int j=0;j<4;j++){
        int o = t + j*256;
        qs[(o>>7)*132 + (o&127)] = g_qk[(size_t)nm*1024 + o];
    }
    if (t < 8) sbs[t] = g_sb[nm*8+t];
    int e0 = g_rowstart[n], e1 = g_rowstart[n+1];
    int h = t & 7, el = t >> 3;
    float run_m = -INFINITY, run_s = 0.f;
    __syncthreads();
    for (int e=e0; e<e1; e+=32){
        for (int idx=t; idx<32*128; idx+=256){
            int er = idx>>7, c = idx&127;
            int ge = e + er;
            efs[er*132+c] = (ge < e1) ? ef[((size_t)ge*MM+m)*128 + c] : 0.f;
        }
        __syncthreads();
        int ge = e + el;
        if (ge < e1){
            float s = sbs[h];
            const float4* a = (const float4*)&efs[el*132];
            const float4* b = (const float4*)&qs[h*132];
            #pragma unroll
            for (int c=0;c<32;c++){
                float4 av = a[c], bv = b[c];
                s += av.x*bv.x + av.y*bv.y + av.z*bv.z + av.w*bv.w;
            }
            g_scores[((size_t)ge*MM+m)*8 + h] = s;
            float nmax = fmaxf(run_m, s);
            run_s = run_s*__expf(run_m - nmax) + __expf(s - nmax);
            run_m = nmax;
        }
        __syncthreads();
    }
    rm[t] = run_m; rs[t] = run_s;
    __syncthreads();
    #pragma unroll
    for (int off=128; off>=8; off>>=1){
        if (t < off){
            float m1 = rm[t], s1 = rs[t];
            float m2 = rm[t+off], s2 = rs[t+off];
            float M = fmaxf(m1, m2);
            float sn = 0.f;
            if (m1 != -INFINITY) sn += s1*__expf(m1 - M);
            if (m2 != -INFINITY) sn += s2*__expf(m2 - M);
            rm[t] = M; rs[t] = sn;
        }
        __syncthreads();
    }
    if (t < 8){ g_mx[nm*8+t] = rm[t]; g_dn[nm*8+t] = rs[t]; }
}

// ---------------- alpha-weighted feature aggregation per (n,m) ----------------
// 128 threads = channel; accumulates u_e[8], u_n[8] per channel
__global__ __launch_bounds__(128) void agg_kernel(
    const float* __restrict__ ef, const float* __restrict__ nf)
{
    int n = blockIdx.x, m = blockIdx.y;
    int nm = n*MM + m;
    int t = threadIdx.x;
    __shared__ float mxs[8], invd[8];
    __shared__ float alph[16*8];
    if (t < 8){
        float dn = g_dn[nm*NH+t];
        mxs[t]  = g_mx[nm*NH+t];
        invd[t] = 1.f/(dn + 1e-16f);
    }
    int e0 = g_rowstart[n], e1 = g_rowstart[n+1];
    float ue[8], un[8];
    #pragma unroll
    for (int i=0;i<8;i++){ ue[i]=0.f; un[i]=0.f; }
    __syncthreads();
    for (int e=e0; e<e1; e+=16){
        int el = t>>3, hh = t&7;
        int ge = e + el;
        alph[t] = (ge < e1) ? __expf(g_scores[((size_t)ge*MM+m)*NH + hh] - mxs[hh])*invd[hh] : 0.f;
        __syncthreads();
        int cnt = min(16, e1 - e);
        for (int j=0;j<cnt;j+=2){
            const float* efp = ef + ((size_t)(e+j)*MM+m)*HH + t;
            const float* nfp = nf + ((size_t)(e+j)*MM+m)*HH + t;
            float fe0 = efp[0], fn0 = nfp[0];
            float fe1 = 0.f, fn1 = 0.f;
            bool two = (j+1 < cnt);
            if (two){ fe1 = efp[MM*HH]; fn1 = nfp[MM*HH]; }
            #pragma unroll
            for (int h2=0;h2<8;h2++){
                float a0 = alph[j*8+h2];
                ue[h2] += a0*fe0; un[h2] += a0*fn0;
            }
            if (two){
                #pragma unroll
                for (int h2=0;h2<8;h2++){
                    float a1 = alph[(j+1)*8+h2];
                    ue[h2] += a1*fe1; un[h2] += a1*fn1;
                }
            }
        }
        __syncthreads();
    }
    #pragma unroll
    for (int h2=0;h2<8;h2++){
        g_ue[((size_t)nm*NH+h2)*HH + t] = ue[h2];
        g_un[((size_t)nm*NH+h2)*HH + t] = un[h2];
    }
}

// ---------------- v transform: agg[:, h*32:+32] = Ue@Wv1 + Un@Wv2 + asum*bv; ego += --
// grid (NM/64, 8 heads); 256 threads = (8 row groups) x (32 cols)
__global__ __launch_bounds__(256) void vtrans_kernel(
    const float* __restrict__ Wv1, const float* __restrict__ bv1,
    const float* __restrict__ Wv2, const float* __restrict__ bv2,
    float* __restrict__ ego)
{
    int h = blockIdx.y;
    int nm0 = blockIdx.x*64;
    int t = threadIdx.x;
    __shared__ float W1s[32*132];
    __shared__ float W2s[32*132];
    for (int idx=t; idx<32*128; idx+=256){
        int j = idx & 31, p = idx >> 5;
        W1s[j*132+p] = Wv1[(size_t)p*256 + h*32 + j];
        W2s[j*132+p] = Wv2[(size_t)p*256 + h*32 + j];
    }
    __syncthreads();
    int ty = t>>5, j = t&31;
    float acc[8];
    #pragma unroll
    for (int i=0;i<8;i++) acc[i] = 0.f;
    const float* ue0 = g_ue + ((size_t)(nm0 + ty*8)*NH + h)*HH;
    const float* un0 = g_un + ((size_t)(nm0 + ty*8)*NH + h)*HH;
    #pragma unroll 4
    for (int p=0;p<128;p+=4){
        float4 w1 = *(const float4*)&W1s[j*132+p];
        float4 w2 = *(const float4*)&W2s[j*132+p];
        #pragma unroll
        for (int i=0;i<8;i++){
            float4 u1 = *(const float4*)(ue0 + (size_t)i*NH*HH + p);
            float4 u2 = *(const float4*)(un0 + (size_t)i*NH*HH + p);
            acc[i] += u1.x*w1.x + u1.y*w1.y + u1.z*w1.z + u1.w*w1.w
                    + u2.x*w2.x + u2.y*w2.y + u2.z*w2.z + u2.w*w2.w;
        }
    }
    float bsum = bv1[h*32+j] + bv2[h*32+j];
    #pragma unroll
    for (int i=0;i<8;i++){
        int nm = nm0 + ty*8 + i;
        float dn = g_dn[nm*NH + h];
        float asum = dn/(dn + 1e-16f);
        ego[(size_t)nm*256 + h*32 + j] += acc[i] + asum*bsum;
    }
}

// ---------------- driver ----------------
extern "C" void kernel_launch(void* const* d_in, const int* in_sizes, int n_in,
                              void* d_out, int out_size)
{
    const int*   batch = (const int*)d_in[0];
    const float* ego_f = (const float*)d_in[1];
    const float* ef    = (const float*)d_in[2];
    const float* nf    = (const float*)d_in[3];
    const float* Wk  = (const float*)d_in[4];
    const float* bk  = (const float*)d_in[5];
    const float* Wq  = (const float*)d_in[6];
    const float* bq  = (const float*)d_in[7];
    const float* Wv1 = (const float*)d_in[8];
    const float* bv1 = (const float*)d_in[9];
    const float* Wv2 = (const float*)d_in[10];
    const float* bv2 = (const float*)d_in[11];
    const float* ln1w= (const float*)d_in[12];
    const float* ln1b= (const float*)d_in[13];
    const float* ln2w= (const float*)d_in[14];
    const float* ln2b= (const float*)d_in[15];
    const float* W1  = (const float*)d_in[16];
    const float* b1  = (const float*)d_in[17];
    const float* W2  = (const float*)d_in[18];
    const float* b2  = (const float*)d_in[19];
    const float* Wd  = (const float*)d_in[20];
    const float* bd  = (const float*)d_in[21];
    float* ego = (float*)d_out;

    cudaMemcpyAsync(ego, ego_f, (size_t)NM*HID*sizeof(float),
                    cudaMemcpyDeviceToDevice, 0);
    rowstart_kernel<<<5, 256>>>(batch);

    dim3 ggemm(NM/64, HID/64);
    for (int i=0;i<3;i++){
        // --- attention block ---
        ln_kernel<<<NM/8, 256>>>(ego, ln1w + i*HID, ln1b + i*HID);
        gemm_kernel<<<ggemm, 256>>>(0, Wq + (size_t)i*HID*HID, bq + i*HID, ego, 0, 0); // g_q = xn@Wq+bq
        qkfold_kernel<<<NM, 256>>>(Wk + (size_t)i*HH*HID, bk + i*HID);
        scores_kernel<<<dim3(NEGO, MM), 256>>>(ef);
        agg_kernel<<<dim3(NEGO, MM), 128>>>(ef, nf);
        vtrans_kernel<<<dim3(NM/64, NH), 256>>>(Wv1 + (size_t)i*HH*HID, bv1 + i*HID,
                                                Wv2 + (size_t)i*HH*HID, bv2 + i*HID, ego);
        // --- ff block ---
        ln_kernel<<<NM/8, 256>>>(ego, ln2w + i*HID, ln2b + i*HID);
        gemm_kernel<<<ggemm, 256>>>(0, W1 + (size_t)i*HID*HID, b1 + i*HID, ego, 1, 1); // hmid=relu
        gemm_kernel<<<ggemm, 256>>>(1, Wd + (size_t)i*HID*HID, bd + i*HID, ego, 0, 0); // g_q=hmid@Wd
        gemm_kernel<<<ggemm, 256>>>(2, W2 + (size_t)i*HID*HID, b2 + i*HID, ego, 2, 0); // ego += @W2
    }
    (void)in_sizes; (void)n_in; (void)out_size;
}

// round 3
// speedup vs baseline: 2.5277x; 2.5277x over previous
#include <cuda_runtime.h>
#include <math.h>

#define NEGO 1024
#define NEDGE 49152
#define MM 6
#define HID 256
#define HH 128
#define NH 8
#define NM (NEGO*MM)
#define LNEPS 1e-5f

// ---------------- scratch (device globals; no allocation allowed) ----------------
__device__ float g_xn[NM*HID];          // LN output (both LN1 and LN2 reuse)
__device__ float g_q[NM*HID];           // q  (also reused as hmid2)
__device__ float g_hmid[NM*HID];        // FF mid
__device__ float g_qk[NM*NH*HH];        // folded q·Wk per node  [nm][h][c]
__device__ float g_sb[NM*NH];           // score bias  bk·q
__device__ float g_scores[NEDGE*MM*NH]; // raw scores
__device__ float g_mx[NM*NH];
__device__ float g_dn[NM*NH];
__device__ float g_ue[NM*NH*HH];        // alpha-weighted edge_feat sums
__device__ float g_un[NM*NH*HH];        // alpha-weighted node_feat sums
__device__ int   g_rowstart[NEGO+1];

// ---------------- segment offsets (batch is sorted) ----------------
__global__ void rowstart_kernel(const int* __restrict__ batch){
    int n = blockIdx.x*blockDim.x + threadIdx.x;
    if (n > NEGO) return;
    int lo = 0, hi = NEDGE;
    while (lo < hi){ int mid = (lo+hi)>>1; if (batch[mid] < n) lo = mid+1; else hi = mid; }
    g_rowstart[n] = lo;
}

// ---------------- LayerNorm: one warp per row of 256 ----------------
__global__ __launch_bounds__(256) void ln_kernel(
    const float* __restrict__ x, const float* __restrict__ w, const float* __restrict__ b)
{
    int warp = threadIdx.x >> 5, lane = threadIdx.x & 31;
    int row = blockIdx.x*8 + warp;
    const float* xr = x + (size_t)row*HID;
    float v[8]; float s = 0.f, s2 = 0.f;
    #pragma unroll
    for (int k=0;k<8;k++){ v[k] = xr[lane + k*32]; s += v[k]; s2 += v[k]*v[k]; }
    #pragma unroll
    for (int o=16;o>0;o>>=1){
        s  += __shfl_xor_sync(0xffffffffu, s,  o);
        s2 += __shfl_xor_sync(0xffffffffu, s2, o);
    }
    float mean = s*(1.f/HID);
    float var  = s2*(1.f/HID) - mean*mean;
    float rstd = rsqrtf(var + LNEPS);
    float* orow = g_xn + (size_t)row*HID;
    #pragma unroll
    for (int k=0;k<8;k++){ int c = lane + k*32; orow[c] = (v[k]-mean)*rstd*w[c] + b[c]; }
}

// ---------------- generic fp32 GEMM: [M,256] @ [256,256] + bias (+relu)(+resid) ----
// Asel: 0=g_xn 1=g_hmid 2=g_q ; Csel: 0=g_q 1=g_hmid 2=ego(+residual)
__global__ __launch_bounds__(256) void gemm_kernel(
    int Asel, const float* __restrict__ W, const float* __restrict__ bias,
    float* __restrict__ ego, int Csel, int relu)
{
    const float* A = (Asel==0) ? g_xn : (Asel==1) ? g_hmid : g_q;
    float*       C = (Csel==0) ? g_q  : (Csel==1) ? g_hmid : ego;
    __shared__ float As[16*68];
    __shared__ float Bs[16*68];
    int t = threadIdx.x;
    int m0 = blockIdx.x*64, n0 = blockIdx.y*64;
    int ty = t>>4, tx = t&15;
    float acc[4][4];
    #pragma unroll
    for (int i=0;i<4;i++)
        #pragma unroll
        for (int j=0;j<4;j++) acc[i][j] = 0.f;
    int ar = t>>2, akc = (t&3)*4;
    int br = t>>4, bc = (t&15)*4;
    const float* Ap = A + (size_t)(m0+ar)*256 + akc;
    const float* Wp = W + (size_t)br*256 + n0 + bc;
    for (int k0=0;k0<256;k0+=16){
        float4 a4 = *(const float4*)(Ap + k0);
        float4 b4 = *(const float4*)(Wp + (size_t)k0*256);
        As[(akc+0)*68+ar] = a4.x;
        As[(akc+1)*68+ar] = a4.y;
        As[(akc+2)*68+ar] = a4.z;
        As[(akc+3)*68+ar] = a4.w;
        *(float4*)&Bs[br*68+bc] = b4;
        __syncthreads();
        #pragma unroll
        for (int k=0;k<16;k++){
            float4 av = *(float4*)&As[k*68+ty*4];
            float4 bv = *(float4*)&Bs[k*68+tx*4];
            float aa[4] = {av.x,av.y,av.z,av.w};
            float bb[4] = {bv.x,bv.y,bv.z,bv.w};
            #pragma unroll
            for (int i=0;i<4;i++)
                #pragma unroll
                for (int j=0;j<4;j++) acc[i][j] += aa[i]*bb[j];
        }
        __syncthreads();
    }
    float4 bb4 = *(const float4*)&bias[n0+tx*4];
    float bi[4] = {bb4.x,bb4.y,bb4.z,bb4.w};
    #pragma unroll
    for (int i=0;i<4;i++){
        int row = m0 + ty*4 + i;
        float ov[4];
        #pragma unroll
        for (int j=0;j<4;j++){
            float v = acc[i][j] + bi[j];
            if (relu) v = fmaxf(v, 0.f);
            ov[j] = v;
        }
        float* cp = C + (size_t)row*256 + n0 + tx*4;
        if (Csel == 2){
            float4 r = *(const float4*)cp;
            ov[0]+=r.x; ov[1]+=r.y; ov[2]+=r.z; ov[3]+=r.w;
        }
        float4 o; o.x=ov[0]; o.y=ov[1]; o.z=ov[2]; o.w=ov[3];
        *(float4*)cp = o;
    }
}

// ---------------- qk fold as per-head tiled GEMM ----------------
// qk[nm,h,c] = sum_d Wk[c, h*32+d] * q[nm, h*32+d];  sb[nm,h] = sum_d bk[h*32+d]*q[nm,h*32+d]
// grid (NM/64, NH); block 256.  Block stages Wk head-slice [128c x 32d] + q tile [64r x 32d].
__global__ __launch_bounds__(256) void qkfold_kernel(
    const float* __restrict__ Wk, const float* __restrict__ bk)
{
    int h = blockIdx.y;
    int nm0 = blockIdx.x*64;
    int t = threadIdx.x;
    __shared__ float Wks[32*129];   // [d][c], pad 129 -> conflict-free
    __shared__ float qs[64*36];     // [r][d], pad 36

    // coalesced load of Wk slice: consecutive t -> consecutive d within a c-row
    for (int idx=t; idx<128*32; idx+=256){
        int c = idx>>5, d = idx&31;
        Wks[d*129 + c] = Wk[(size_t)c*256 + h*32 + d];
    }
    // coalesced load of q tile
    for (int idx=t; idx<64*32; idx+=256){
        int r = idx>>5, d = idx&31;
        qs[r*36 + d] = g_q[(size_t)(nm0+r)*256 + h*32 + d];
    }
    __syncthreads();

    int tx = t&31, ty = t>>5;   // ty: 8 row-groups, tx: 32 cols
    float acc[8][4];
    #pragma unroll
    for (int i=0;i<8;i++)
        #pragma unroll
        for (int j=0;j<4;j++) acc[i][j] = 0.f;

    #pragma unroll 8
    for (int d=0; d<32; d++){
        float w0 = Wks[d*129 + tx];
        float w1 = Wks[d*129 + tx + 32];
        float w2 = Wks[d*129 + tx + 64];
        float w3 = Wks[d*129 + tx + 96];
        #pragma unroll
        for (int i=0;i<8;i++){
            float qv = qs[(ty*8+i)*36 + d];    // broadcast within warp
            acc[i][0] += qv*w0;
            acc[i][1] += qv*w1;
            acc[i][2] += qv*w2;
            acc[i][3] += qv*w3;
        }
    }

    #pragma unroll
    for (int i=0;i<8;i++){
        float* outp = g_qk + (size_t)(nm0 + ty*8 + i)*1024 + h*128 + tx;
        #pragma unroll
        for (int j=0;j<4;j++) outp[j*32] = acc[i][j];
    }

    if (t < 64){
        float s = 0.f;
        #pragma unroll
        for (int d=0;d<32;d++) s += bk[h*32+d]*qs[t*36 + d];
        g_sb[(nm0+t)*NH + h] = s;
    }
}

// ---------------- scores + fused online segment-softmax stats ----------------
// block per (n,m); 256 threads = (32 edge slots) x (8 heads)
__global__ __launch_bounds__(256) void scores_kernel(const float* __restrict__ ef)
{
    int n = blockIdx.x, m = blockIdx.y;
    int nm = n*MM + m;
    int t = threadIdx.x;
    __shared__ float qs[8*132];
    __shared__ float sbs[8];
    __shared__ float efs[32*132];
    __shared__ float rm[256], rs[256];
    #pragma unroll
    for (int j=0;j<4;j++){
        int o = t + j*256;
        qs[(o>>7)*132 + (o&127)] = g_qk[(size_t)nm*1024 + o];
    }
    if (t < 8) sbs[t] = g_sb[nm*8+t];
    int e0 = g_rowstart[n], e1 = g_rowstart[n+1];
    int h = t & 7, el = t >> 3;
    float run_m = -INFINITY, run_s = 0.f;
    __syncthreads();
    for (int e=e0; e<e1; e+=32){
        for (int idx=t; idx<32*128; idx+=256){
            int er = idx>>7, c = idx&127;
            int ge = e + er;
            efs[er*132+c] = (ge < e1) ? ef[((size_t)ge*MM+m)*128 + c] : 0.f;
        }
        __syncthreads();
        int ge = e + el;
        if (ge < e1){
            float s = sbs[h];
            const float4* a = (const float4*)&efs[el*132];
            const float4* b = (const float4*)&qs[h*132];
            #pragma unroll
            for (int c=0;c<32;c++){
                float4 av = a[c], bv = b[c];
                s += av.x*bv.x + av.y*bv.y + av.z*bv.z + av.w*bv.w;
            }
            g_scores[((size_t)ge*MM+m)*8 + h] = s;
            float nmax = fmaxf(run_m, s);
            run_s = run_s*__expf(run_m - nmax) + __expf(s - nmax);
            run_m = nmax;
        }
        __syncthreads();
    }
    rm[t] = run_m; rs[t] = run_s;
    __syncthreads();
    #pragma unroll
    for (int off=128; off>=8; off>>=1){
        if (t < off){
            float m1 = rm[t], s1 = rs[t];
            float m2 = rm[t+off], s2 = rs[t+off];
            float M = fmaxf(m1, m2);
            float sn = 0.f;
            if (m1 != -INFINITY) sn += s1*__expf(m1 - M);
            if (m2 != -INFINITY) sn += s2*__expf(m2 - M);
            rm[t] = M; rs[t] = sn;
        }
        __syncthreads();
    }
    if (t < 8){ g_mx[nm*8+t] = rm[t]; g_dn[nm*8+t] = rs[t]; }
}

// ---------------- alpha-weighted feature aggregation per (n,m) ----------------
// 128 threads = channel; accumulates u_e[8], u_n[8] per channel
__global__ __launch_bounds__(128) void agg_kernel(
    const float* __restrict__ ef, const float* __restrict__ nf)
{
    int n = blockIdx.x, m = blockIdx.y;
    int nm = n*MM + m;
    int t = threadIdx.x;
    __shared__ float mxs[8], invd[8];
    __shared__ float alph[16*8];
    if (t < 8){
        float dn = g_dn[nm*NH+t];
        mxs[t]  = g_mx[nm*NH+t];
        invd[t] = 1.f/(dn + 1e-16f);
    }
    int e0 = g_rowstart[n], e1 = g_rowstart[n+1];
    float ue[8], un[8];
    #pragma unroll
    for (int i=0;i<8;i++){ ue[i]=0.f; un[i]=0.f; }
    __syncthreads();
    for (int e=e0; e<e1; e+=16){
        int el = t>>3, hh = t&7;
        int ge = e + el;
        alph[t] = (ge < e1) ? __expf(g_scores[((size_t)ge*MM+m)*NH + hh] - mxs[hh])*invd[hh] : 0.f;
        __syncthreads();
        int cnt = min(16, e1 - e);
        for (int j=0;j<cnt;j+=2){
            const float* efp = ef + ((size_t)(e+j)*MM+m)*HH + t;
            const float* nfp = nf + ((size_t)(e+j)*MM+m)*HH + t;
            float fe0 = efp[0], fn0 = nfp[0];
            float fe1 = 0.f, fn1 = 0.f;
            bool two = (j+1 < cnt);
            if (two){ fe1 = efp[MM*HH]; fn1 = nfp[MM*HH]; }
            #pragma unroll
            for (int h2=0;h2<8;h2++){
                float a0 = alph[j*8+h2];
                ue[h2] += a0*fe0; un[h2] += a0*fn0;
            }
            if (two){
                #pragma unroll
                for (int h2=0;h2<8;h2++){
                    float a1 = alph[(j+1)*8+h2];
                    ue[h2] += a1*fe1; un[h2] += a1*fn1;
                }
            }
        }
        __syncthreads();
    }
    #pragma unroll
    for (int h2=0;h2<8;h2++){
        g_ue[((size_t)nm*NH+h2)*HH + t] = ue[h2];
        g_un[((size_t)nm*NH+h2)*HH + t] = un[h2];
    }
}

// ---------------- v transform: agg[:, h*32:+32] = Ue@Wv1 + Un@Wv2 + asum*bv; ego += --
// grid (NM/64, 8 heads); 256 threads = (8 row groups) x (32 cols)
__global__ __launch_bounds__(256) void vtrans_kernel(
    const float* __restrict__ Wv1, const float* __restrict__ bv1,
    const float* __restrict__ Wv2, const float* __restrict__ bv2,
    float* __restrict__ ego)
{
    int h = blockIdx.y;
    int nm0 = blockIdx.x*64;
    int t = threadIdx.x;
    __shared__ float W1s[32*132];
    __shared__ float W2s[32*132];
    for (int idx=t; idx<32*128; idx+=256){
        int j = idx & 31, p = idx >> 5;
        W1s[j*132+p] = Wv1[(size_t)p*256 + h*32 + j];
        W2s[j*132+p] = Wv2[(size_t)p*256 + h*32 + j];
    }
    __syncthreads();
    int ty = t>>5, j = t&31;
    float acc[8];
    #pragma unroll
    for (int i=0;i<8;i++) acc[i] = 0.f;
    const float* ue0 = g_ue + ((size_t)(nm0 + ty*8)*NH + h)*HH;
    const float* un0 = g_un + ((size_t)(nm0 + ty*8)*NH + h)*HH;
    #pragma unroll 4
    for (int p=0;p<128;p+=4){
        float4 w1 = *(const float4*)&W1s[j*132+p];
        float4 w2 = *(const float4*)&W2s[j*132+p];
        #pragma unroll
        for (int i=0;i<8;i++){
            float4 u1 = *(const float4*)(ue0 + (size_t)i*NH*HH + p);
            float4 u2 = *(const float4*)(un0 + (size_t)i*NH*HH + p);
            acc[i] += u1.x*w1.x + u1.y*w1.y + u1.z*w1.z + u1.w*w1.w
                    + u2.x*w2.x + u2.y*w2.y + u2.z*w2.z + u2.w*w2.w;
        }
    }
    float bsum = bv1[h*32+j] + bv2[h*32+j];
    #pragma unroll
    for (int i=0;i<8;i++){
        int nm = nm0 + ty*8 + i;
        float dn = g_dn[nm*NH + h];
        float asum = dn/(dn + 1e-16f);
        ego[(size_t)nm*256 + h*32 + j] += acc[i] + asum*bsum;
    }
}

// ---------------- driver ----------------
extern "C" void kernel_launch(void* const* d_in, const int* in_sizes, int n_in,
                              void* d_out, int out_size)
{
    const int*   batch = (const int*)d_in[0];
    const float* ego_f = (const float*)d_in[1];
    const float* ef    = (const float*)d_in[2];
    const float* nf    = (const float*)d_in[3];
    const float* Wk  = (const float*)d_in[4];
    const float* bk  = (const float*)d_in[5];
    const float* Wq  = (const float*)d_in[6];
    const float* bq  = (const float*)d_in[7];
    const float* Wv1 = (const float*)d_in[8];
    const float* bv1 = (const float*)d_in[9];
    const float* Wv2 = (const float*)d_in[10];
    const float* bv2 = (const float*)d_in[11];
    const float* ln1w= (const float*)d_in[12];
    const float* ln1b= (const float*)d_in[13];
    const float* ln2w= (const float*)d_in[14];
    const float* ln2b= (const float*)d_in[15];
    const float* W1  = (const float*)d_in[16];
    const float* b1  = (const float*)d_in[17];
    const float* W2  = (const float*)d_in[18];
    const float* b2  = (const float*)d_in[19];
    const float* Wd  = (const float*)d_in[20];
    const float* bd  = (const float*)d_in[21];
    float* ego = (float*)d_out;

    cudaMemcpyAsync(ego, ego_f, (size_t)NM*HID*sizeof(float),
                    cudaMemcpyDeviceToDevice, 0);
    rowstart_kernel<<<5, 256>>>(batch);

    dim3 ggemm(NM/64, HID/64);
    for (int i=0;i<3;i++){
        // --- attention block ---
        ln_kernel<<<NM/8, 256>>>(ego, ln1w + i*HID, ln1b + i*HID);
        gemm_kernel<<<ggemm, 256>>>(0, Wq + (size_t)i*HID*HID, bq + i*HID, ego, 0, 0); // g_q = xn@Wq+bq
        qkfold_kernel<<<dim3(NM/64, NH), 256>>>(Wk + (size_t)i*HH*HID, bk + i*HID);
        scores_kernel<<<dim3(NEGO, MM), 256>>>(ef);
        agg_kernel<<<dim3(NEGO, MM), 128>>>(ef, nf);
        vtrans_kernel<<<dim3(NM/64, NH), 256>>>(Wv1 + (size_t)i*HH*HID, bv1 + i*HID,
                                                Wv2 + (size_t)i*HH*HID, bv2 + i*HID, ego);
        // --- ff block ---
        ln_kernel<<<NM/8, 256>>>(ego, ln2w + i*HID, ln2b + i*HID);
        gemm_kernel<<<ggemm, 256>>>(0, W1 + (size_t)i*HID*HID, b1 + i*HID, ego, 1, 1); // hmid=relu
        gemm_kernel<<<ggemm, 256>>>(1, Wd + (size_t)i*HID*HID, bd + i*HID, ego, 0, 0); // g_q=hmid@Wd
        gemm_kernel<<<ggemm, 256>>>(2, W2 + (size_t)i*HID*HID, b2 + i*HID, ego, 2, 0); // ego += @W2
    }
    (void)in_sizes; (void)n_in; (void)out_size;
}

// round 10
// speedup vs baseline: 2.9222x; 1.1561x over previous
#include <cuda_runtime.h>
#include <math.h>

#define NEGO 1024
#define NEDGE 49152
#define MM 6
#define HID 256
#define HH 128
#define NH 8
#define NM (NEGO*MM)
#define LNEPS 1e-5f

typedef unsigned long long ull;
union F2U { ull u; float2 f; };

__device__ __forceinline__ void fma2(ull &d, ull a, ull b){
    asm("fma.rn.f32x2 %0, %1, %2, %0;" : "+l"(d) : "l"(a), "l"(b));
}
__device__ __forceinline__ ull pack2(float x, float y){
    ull r; asm("mov.b64 %0, {%1,%2};" : "=l"(r) : "f"(x), "f"(y)); return r;
}
__device__ __forceinline__ ull d2u(double d){ return __double_as_longlong(d); }

// ---------------- scratch ----------------
__device__ float g_q[NM*HID];
__device__ float g_hmid[NM*HID];
__device__ float g_qk[NM*NH*HH];
__device__ float g_sb[NM*NH];
__device__ float g_scores[NEDGE*MM*NH];
__device__ float g_mx[NM*NH];
__device__ float g_dn[NM*NH];
__device__ float g_ue[NM*NH*HH];
__device__ float g_un[NM*NH*HH];
__device__ float g_mu[NM];
__device__ float g_rs[NM];
__device__ int   g_rowstart[NEGO+1];
// folded / composed weights
__device__ float g_Wqf[3*HID*HID];
__device__ float g_bqf[3*HID];
__device__ float g_W1f[3*HID*HID];
__device__ float g_b1f[3*HID];
__device__ float g_Wc[3*HID*HID];
__device__ float g_bc[3*HID];

// ---------------- segment offsets ----------------
__global__ void rowstart_kernel(const int* __restrict__ batch){
    int n = blockIdx.x*blockDim.x + threadIdx.x;
    if (n > NEGO) return;
    int lo = 0, hi = NEDGE;
    while (lo < hi){ int mid = (lo+hi)>>1; if (batch[mid] < n) lo = mid+1; else hi = mid; }
    g_rowstart[n] = lo;
}

// ---------------- per-row LN stats ----------------
__global__ __launch_bounds__(256) void stats_kernel(const float* __restrict__ x){
    int warp = threadIdx.x >> 5, lane = threadIdx.x & 31;
    int row = blockIdx.x*8 + warp;
    const float* xr = x + (size_t)row*HID;
    float s = 0.f, s2 = 0.f;
    #pragma unroll
    for (int k=0;k<8;k++){ float v = xr[lane + k*32]; s += v; s2 += v*v; }
    #pragma unroll
    for (int o=16;o>0;o>>=1){
        s  += __shfl_xor_sync(0xffffffffu, s,  o);
        s2 += __shfl_xor_sync(0xffffffffu, s2, o);
    }
    if (lane == 0){
        float mean = s*(1.f/HID);
        float var  = s2*(1.f/HID) - mean*mean;
        g_mu[row] = mean;
        g_rs[row] = rsqrtf(var + LNEPS);
    }
}

// ---------------- fold LN weights:  W' = diag(lnw)@W ; b' = lnb@W + b ----------------
__global__ __launch_bounds__(256) void foldln_kernel(
    const float* __restrict__ Wq, const float* __restrict__ bq,
    const float* __restrict__ ln1w, const float* __restrict__ ln1b,
    const float* __restrict__ W1, const float* __restrict__ b1,
    const float* __restrict__ ln2w, const float* __restrict__ ln2b)
{
    int jc = blockIdx.x*64, which = blockIdx.y, l = blockIdx.z;
    const float* W  = (which==0 ? Wq : W1) + (size_t)l*65536;
    const float* bb = (which==0 ? bq : b1) + l*256;
    const float* lw = (which==0 ? ln1w : ln2w) + l*256;
    const float* lb = (which==0 ? ln1b : ln2b) + l*256;
    float* Wo = (which==0 ? g_Wqf : g_W1f) + (size_t)l*65536;
    float* bo = (which==0 ? g_bqf : g_b1f) + l*256;
    __shared__ float lws[256], lbs[256], red[4][64];
    int t = threadIdx.x;
    lws[t] = lw[t]; lbs[t] = lb[t];
    __syncthreads();
    int j = jc + (t&63), kq = t>>6;
    float bacc = 0.f;
    for (int k=kq; k<256; k+=4){
        float w = W[(size_t)k*256 + j];
        Wo[(size_t)k*256 + j] = lws[k]*w;
        bacc += lbs[k]*w;
    }
    red[kq][t&63] = bacc;
    __syncthreads();
    if (t < 64)
        bo[jc+t] = red[0][t]+red[1][t]+red[2][t]+red[3][t] + bb[jc+t];
}

// ---------------- compose Wc = Wd @ W2 ----------------
__global__ __launch_bounds__(256) void compose_kernel(
    const float* __restrict__ Wd, const float* __restrict__ W2)
{
    int l = blockIdx.z;
    const float* A = Wd + (size_t)l*65536;
    const float* B = W2 + (size_t)l*65536;
    float* C = g_Wc + (size_t)l*65536;
    __shared__ float As[16*68];
    __shared__ float Bs[16*68];
    int t = threadIdx.x;
    int m0 = blockIdx.x*64, n0 = blockIdx.y*64;
    int ty = t>>4, tx = t&15;
    float acc[4][4];
    #pragma unroll
    for (int i=0;i<4;i++)
        #pragma unroll
        for (int j=0;j<4;j++) acc[i][j] = 0.f;
    int ar = t>>2, akc = (t&3)*4;
    int br = t>>4, bc = (t&15)*4;
    const float* Ap = A + (size_t)(m0+ar)*256 + akc;
    const float* Bp = B + (size_t)br*256 + n0 + bc;
    for (int k0=0;k0<256;k0+=16){
        float4 a4 = *(const float4*)(Ap + k0);
        float4 b4 = *(const float4*)(Bp + (size_t)k0*256);
        As[(akc+0)*68+ar] = a4.x; As[(akc+1)*68+ar] = a4.y;
        As[(akc+2)*68+ar] = a4.z; As[(akc+3)*68+ar] = a4.w;
        *(float4*)&Bs[br*68+bc] = b4;
        __syncthreads();
        #pragma unroll
        for (int k=0;k<16;k++){
            float4 av = *(float4*)&As[k*68+ty*4];
            float4 bv = *(float4*)&Bs[k*68+tx*4];
            float aa[4] = {av.x,av.y,av.z,av.w};
            float bb[4] = {bv.x,bv.y,bv.z,bv.w};
            #pragma unroll
            for (int i=0;i<4;i++)
                #pragma unroll
                for (int j=0;j<4;j++) acc[i][j] += aa[i]*bb[j];
        }
        __syncthreads();
    }
    #pragma unroll
    for (int i=0;i<4;i++){
        float4 o; o.x=acc[i][0]; o.y=acc[i][1]; o.z=acc[i][2]; o.w=acc[i][3];
        *(float4*)(C + (size_t)(m0+ty*4+i)*256 + n0 + tx*4) = o;
    }
}

// bc = bd @ W2 + b2
__global__ __launch_bounds__(256) void composebias_kernel(
    const float* __restrict__ bd, const float* __restrict__ W2, const float* __restrict__ b2)
{
    int jc = blockIdx.x*64, l = blockIdx.y;
    const float* B = W2 + (size_t)l*65536;
    __shared__ float bds[256], red[4][64];
    int t = threadIdx.x;
    bds[t] = bd[l*256 + t];
    __syncthreads();
    int j = jc + (t&63), kq = t>>6;
    float acc = 0.f;
    for (int k=kq;k<256;k+=4) acc += bds[k]*B[(size_t)k*256 + j];
    red[kq][t&63] = acc;
    __syncthreads();
    if (t < 64)
        g_bc[l*256 + jc + t] = red[0][t]+red[1][t]+red[2][t]+red[3][t] + b2[l*256+jc+t];
}

// ---------------- main GEMM: [6144,256] @ [256,256], f32x2 row-pair ----------------
// 64x64 tile, 128 threads. ty=t>>4 (8 row-groups of 8 rows), tx=t&15 (4 cols).
// acc[p][c]: f32x2 = rows (ty*8+2p, ty*8+2p+1), col n0+tx*4+c.
// B duplication done in-register via pack2 (no skew, all smem ops 16B-aligned).
__global__ __launch_bounds__(128) void gemm_kernel(
    int Asel, int Wsel, int layer, float* __restrict__ ego, int Csel, int relu)
{
    const float* A = (Asel==0) ? ego : g_hmid;
    const float* W = ((Wsel==0)? g_Wqf : (Wsel==1)? g_W1f : g_Wc) + (size_t)layer*65536;
    const float* bias = ((Wsel==0)? g_bqf : (Wsel==1)? g_b1f : g_bc) + layer*256;
    float* C = (Csel==0)? g_q : (Csel==1)? g_hmid : ego;

    __shared__ __align__(16) float As[16*68];   // [k][row]  (68*4=272=17*16 -> rows aligned)
    __shared__ __align__(16) float Bs[16*68];   // [k][col]

    int t = threadIdx.x;
    int m0 = blockIdx.x*64, n0 = blockIdx.y*64;
    int ty = t>>4, tx = t&15;

    ull acc[4][4];
    #pragma unroll
    for (int p=0;p<4;p++)
        #pragma unroll
        for (int c=0;c<4;c++) acc[p][c] = 0ull;

    int sr0 = t>>2, skc = (t&3)*4;   int sr1 = sr0 + 32;
    int br = t>>4, bc = (t&15)*4;    int br1 = br + 8;
    float mua=0.f, rsa=1.f, mub=0.f, rsb=1.f;
    if (Asel==0){
        mua = g_mu[m0+sr0]; rsa = g_rs[m0+sr0];
        mub = g_mu[m0+sr1]; rsb = g_rs[m0+sr1];
    }
    const float* Ap0 = A + (size_t)(m0+sr0)*256 + skc;
    const float* Ap1 = A + (size_t)(m0+sr1)*256 + skc;
    const float* Wp0 = W + (size_t)br*256 + n0 + bc;
    const float* Wp1 = W + (size_t)br1*256 + n0 + bc;

    for (int k0=0;k0<256;k0+=16){
        float4 a0 = *(const float4*)(Ap0 + k0);
        float4 a1 = *(const float4*)(Ap1 + k0);
        float4 w0 = *(const float4*)(Wp0 + (size_t)k0*256);
        float4 w1 = *(const float4*)(Wp1 + (size_t)k0*256);
        if (Asel==0){
            a0.x=(a0.x-mua)*rsa; a0.y=(a0.y-mua)*rsa; a0.z=(a0.z-mua)*rsa; a0.w=(a0.w-mua)*rsa;
            a1.x=(a1.x-mub)*rsb; a1.y=(a1.y-mub)*rsb; a1.z=(a1.z-mub)*rsb; a1.w=(a1.w-mub)*rsb;
        }
        __syncthreads();
        As[(skc+0)*68+sr0]=a0.x; As[(skc+1)*68+sr0]=a0.y;
        As[(skc+2)*68+sr0]=a0.z; As[(skc+3)*68+sr0]=a0.w;
        As[(skc+0)*68+sr1]=a1.x; As[(skc+1)*68+sr1]=a1.y;
        As[(skc+2)*68+sr1]=a1.z; As[(skc+3)*68+sr1]=a1.w;
        *(float4*)&Bs[br*68 + bc]  = w0;
        *(float4*)&Bs[br1*68 + bc] = w1;
        __syncthreads();
        #pragma unroll
        for (int k=0;k<16;k++){
            double2 av0 = *(const double2*)&As[k*68 + ty*8];      // 16B aligned, warp-broadcast
            double2 av1 = *(const double2*)&As[k*68 + ty*8 + 4];
            float4  bv  = *(const float4*)&Bs[k*68 + tx*4];       // contiguous 256B/warp
            ull a01=d2u(av0.x), a23=d2u(av0.y), a45=d2u(av1.x), a67=d2u(av1.y);
            ull b0=pack2(bv.x,bv.x), b1=pack2(bv.y,bv.y), b2=pack2(bv.z,bv.z), b3=pack2(bv.w,bv.w);
            fma2(acc[0][0],a01,b0); fma2(acc[0][1],a01,b1); fma2(acc[0][2],a01,b2); fma2(acc[0][3],a01,b3);
            fma2(acc[1][0],a23,b0); fma2(acc[1][1],a23,b1); fma2(acc[1][2],a23,b2); fma2(acc[1][3],a23,b3);
            fma2(acc[2][0],a45,b0); fma2(acc[2][1],a45,b1); fma2(acc[2][2],a45,b2); fma2(acc[2][3],a45,b3);
            fma2(acc[3][0],a67,b0); fma2(acc[3][1],a67,b1); fma2(acc[3][2],a67,b2); fma2(acc[3][3],a67,b3);
        }
    }

    float4 bb = *(const float4*)&bias[n0 + tx*4];
    #pragma unroll
    for (int p=0;p<4;p++){
        F2U u0,u1,u2,u3;
        u0.u=acc[p][0]; u1.u=acc[p][1]; u2.u=acc[p][2]; u3.u=acc[p][3];
        int re = m0 + ty*8 + 2*p;
        float4 oe, oo;
        oe.x=u0.f.x+bb.x; oe.y=u1.f.x+bb.y; oe.z=u2.f.x+bb.z; oe.w=u3.f.x+bb.w;
        oo.x=u0.f.y+bb.x; oo.y=u1.f.y+bb.y; oo.z=u2.f.y+bb.z; oo.w=u3.f.y+bb.w;
        if (relu){
            oe.x=fmaxf(oe.x,0.f); oe.y=fmaxf(oe.y,0.f); oe.z=fmaxf(oe.z,0.f); oe.w=fmaxf(oe.w,0.f);
            oo.x=fmaxf(oo.x,0.f); oo.y=fmaxf(oo.y,0.f); oo.z=fmaxf(oo.z,0.f); oo.w=fmaxf(oo.w,0.f);
        }
        float* cpe = C + (size_t)re*256 + n0 + tx*4;
        float* cpo = cpe + 256;
        if (Csel == 2){
            float4 r0 = *(const float4*)cpe;
            float4 r1 = *(const float4*)cpo;
            oe.x+=r0.x; oe.y+=r0.y; oe.z+=r0.z; oe.w+=r0.w;
            oo.x+=r1.x; oo.y+=r1.y; oo.z+=r1.z; oo.w+=r1.w;
        }
        *(float4*)cpe = oe;
        *(float4*)cpo = oo;
    }
}

// ---------------- qk fold per-head GEMM, f32x2 ----------------
__global__ __launch_bounds__(256) void qkfold_kernel(
    const float* __restrict__ Wk, const float* __restrict__ bk)
{
    int h = blockIdx.y;
    int nm0 = blockIdx.x*64;
    int t = threadIdx.x;
    __shared__ __align__(16) float Wks[32*129];   // [d][c]
    __shared__ __align__(16) float qs[32*72];     // [d][r]  (72*4=288=18*16 aligned)

    for (int idx=t; idx<128*32; idx+=256){
        int c = idx>>5, d = idx&31;
        Wks[d*129 + c] = Wk[(size_t)c*256 + h*32 + d];
    }
    for (int idx=t; idx<64*32; idx+=256){
        int r = idx>>5, d = idx&31;
        qs[d*72 + r] = g_q[(size_t)(nm0+r)*256 + h*32 + d];
    }
    __syncthreads();

    int tx = t&31, ty = t>>5;
    ull acc[4][4];
    #pragma unroll
    for (int p=0;p<4;p++)
        #pragma unroll
        for (int j=0;j<4;j++) acc[p][j] = 0ull;

    #pragma unroll 8
    for (int d=0; d<32; d++){
        double2 av0 = *(const double2*)&qs[d*72 + ty*8];
        double2 av1 = *(const double2*)&qs[d*72 + ty*8 + 4];
        ull a01=d2u(av0.x), a23=d2u(av0.y), a45=d2u(av1.x), a67=d2u(av1.y);
        float w0 = Wks[d*129 + tx];
        float w1 = Wks[d*129 + tx + 32];
        float w2 = Wks[d*129 + tx + 64];
        float w3 = Wks[d*129 + tx + 96];
        ull wd0=pack2(w0,w0), wd1=pack2(w1,w1), wd2=pack2(w2,w2), wd3=pack2(w3,w3);
        fma2(acc[0][0],a01,wd0); fma2(acc[0][1],a01,wd1); fma2(acc[0][2],a01,wd2); fma2(acc[0][3],a01,wd3);
        fma2(acc[1][0],a23,wd0); fma2(acc[1][1],a23,wd1); fma2(acc[1][2],a23,wd2); fma2(acc[1][3],a23,wd3);
        fma2(acc[2][0],a45,wd0); fma2(acc[2][1],a45,wd1); fma2(acc[2][2],a45,wd2); fma2(acc[2][3],a45,wd3);
        fma2(acc[3][0],a67,wd0); fma2(acc[3][1],a67,wd1); fma2(acc[3][2],a67,wd2); fma2(acc[3][3],a67,wd3);
    }

    #pragma unroll
    for (int p=0;p<4;p++){
        #pragma unroll
        for (int j=0;j<4;j++){
            F2U u; u.u = acc[p][j];
            float* base = g_qk + (size_t)(nm0 + ty*8 + 2*p)*1024 + h*128 + tx + 32*j;
            base[0]    = u.f.x;
            base[1024] = u.f.y;
        }
    }

    if (t < 64){
        float s = 0.f;
        #pragma unroll
        for (int d=0;d<32;d++) s += bk[h*32+d]*qs[d*72 + t];
        g_sb[(nm0+t)*NH + h] = s;
    }
}

// ---------------- scores + fused online segment-softmax stats ----------------
__global__ __launch_bounds__(256) void scores_kernel(const float* __restrict__ ef)
{
    int n = blockIdx.x, m = blockIdx.y;
    int nm = n*MM + m;
    int t = threadIdx.x;
    __shared__ __align__(16) float qs[8*132];     // 132*4=528=33*16 aligned
    __shared__ float sbs[8];
    __shared__ __align__(16) float efs[32*132];
    __shared__ float rm[256], rs[256];
    #pragma unroll
    for (int j=0;j<4;j++){
        int o = t + j*256;
        qs[(o>>7)*132 + (o&127)] = g_qk[(size_t)nm*1024 + o];
    }
    if (t < 8) sbs[t] = g_sb[nm*8+t];
    int e0 = g_rowstart[n], e1 = g_rowstart[n+1];
    int h = t & 7, el = t >> 3;
    float run_m = -INFINITY, run_s = 0.f;
    __syncthreads();
    for (int e=e0; e<e1; e+=32){
        for (int idx=t; idx<32*128; idx+=256){
            int er = idx>>7, c = idx&127;
            int ge = e + er;
            efs[er*132+c] = (ge < e1) ? ef[((size_t)ge*MM+m)*128 + c] : 0.f;
        }
        __syncthreads();
        int ge = e + el;
        if (ge < e1){
            ull acca = 0ull, accb = 0ull;
            const double2* a = (const double2*)&efs[el*132];
            const double2* b = (const double2*)&qs[h*132];
            #pragma unroll
            for (int c=0;c<32;c++){               // 32 double2 = 128 floats
                double2 av = a[c], bv = b[c];
                fma2(acca, d2u(av.x), d2u(bv.x));
                fma2(accb, d2u(av.y), d2u(bv.y));
            }
            F2U ua, ub; ua.u = acca; ub.u = accb;
            float s = sbs[h] + ua.f.x + ua.f.y + ub.f.x + ub.f.y;
            g_scores[((size_t)ge*MM+m)*8 + h] = s;
            float nmax = fmaxf(run_m, s);
            run_s = run_s*__expf(run_m - nmax) + __expf(s - nmax);
            run_m = nmax;
        }
        __syncthreads();
    }
    rm[t] = run_m; rs[t] = run_s;
    __syncthreads();
    #pragma unroll
    for (int off=128; off>=8; off>>=1){
        if (t < off){
            float m1 = rm[t], s1 = rs[t];
            float m2 = rm[t+off], s2 = rs[t+off];
            float M = fmaxf(m1, m2);
            float sn = 0.f;
            if (m1 != -INFINITY) sn += s1*__expf(m1 - M);
            if (m2 != -INFINITY) sn += s2*__expf(m2 - M);
            rm[t] = M; rs[t] = sn;
        }
        __syncthreads();
    }
    if (t < 8){ g_mx[nm*8+t] = rm[t]; g_dn[nm*8+t] = rs[t]; }
}

// ---------------- alpha-weighted feature aggregation, f32x2 ----------------
__global__ __launch_bounds__(128) void agg_kernel(
    const float* __restrict__ ef, const float* __restrict__ nf)
{
    int n = blockIdx.x, m = blockIdx.y;
    int nm = n*MM + m;
    int t = threadIdx.x;
    __shared__ float mxs[8], invd[8];
    __shared__ __align__(16) float alph[16*8];
    if (t < 8){
        float dn = g_dn[nm*NH+t];
        mxs[t]  = g_mx[nm*NH+t];
        invd[t] = 1.f/(dn + 1e-16f);
    }
    int e0 = g_rowstart[n], e1 = g_rowstart[n+1];
    ull ue2[4], un2[4];
    #pragma unroll
    for (int i=0;i<4;i++){ ue2[i]=0ull; un2[i]=0ull; }
    __syncthreads();
    for (int e=e0; e<e1; e+=16){
        int el = t>>3, hh = t&7;
        int ge = e + el;
        alph[t] = (ge < e1) ? __expf(g_scores[((size_t)ge*MM+m)*NH + hh] - mxs[hh])*invd[hh] : 0.f;
        __syncthreads();
        #pragma unroll
        for (int jj=0; jj<16; jj+=8){
            float fe[8], fn[8];
            #pragma unroll
            for (int u=0;u<8;u++){
                int ge2 = e + jj + u;
                bool ok = (ge2 < e1);
                fe[u] = ok ? ef[((size_t)ge2*MM+m)*HH + t] : 0.f;
                fn[u] = ok ? nf[((size_t)ge2*MM+m)*HH + t] : 0.f;
            }
            #pragma unroll
            for (int u=0;u<8;u++){
                ull fed = pack2(fe[u], fe[u]);
                ull fnd = pack2(fn[u], fn[u]);
                double2 al0 = *(const double2*)&alph[(jj+u)*8];
                double2 al1 = *(const double2*)&alph[(jj+u)*8 + 4];
                ull a01=d2u(al0.x), a23=d2u(al0.y), a45=d2u(al1.x), a67=d2u(al1.y);
                fma2(ue2[0],a01,fed); fma2(ue2[1],a23,fed); fma2(ue2[2],a45,fed); fma2(ue2[3],a67,fed);
                fma2(un2[0],a01,fnd); fma2(un2[1],a23,fnd); fma2(un2[2],a45,fnd); fma2(un2[3],a67,fnd);
            }
        }
        __syncthreads();
    }
    #pragma unroll
    for (int i=0;i<4;i++){
        F2U ue, un; ue.u = ue2[i]; un.u = un2[i];
        g_ue[((size_t)nm*NH + 2*i  )*HH + t] = ue.f.x;
        g_ue[((size_t)nm*NH + 2*i+1)*HH + t] = ue.f.y;
        g_un[((size_t)nm*NH + 2*i  )*HH + t] = un.f.x;
        g_un[((size_t)nm*NH + 2*i+1)*HH + t] = un.f.y;
    }
}

// ---------------- v transform ----------------
__global__ __launch_bounds__(256) void vtrans_kernel(
    const float* __restrict__ Wv1, const float* __restrict__ bv1,
    const float* __restrict__ Wv2, const float* __restrict__ bv2,
    float* __restrict__ ego)
{
    int h = blockIdx.y;
    int nm0 = blockIdx.x*64;
    int t = threadIdx.x;
    __shared__ float W1s[32*132];
    __shared__ float W2s[32*132];
    for (int idx=t; idx<32*128; idx+=256){
        int j = idx & 31, p = idx >> 5;
        W1s[j*132+p] = Wv1[(size_t)p*256 + h*32 + j];
        W2s[j*132+p] = Wv2[(size_t)p*256 + h*32 + j];
    }
    __syncthreads();
    int ty = t>>5, j = t&31;
    float acc[8];
    #pragma unroll
    for (int i=0;i<8;i++) acc[i] = 0.f;
    const float* ue0 = g_ue + ((size_t)(nm0 + ty*8)*NH + h)*HH;
    const float* un0 = g_un + ((size_t)(nm0 + ty*8)*NH + h)*HH;
    #pragma unroll 4
    for (int p=0;p<128;p+=4){
        float4 w1 = *(const float4*)&W1s[j*132+p];
        float4 w2 = *(const float4*)&W2s[j*132+p];
        #pragma unroll
        for (int i=0;i<8;i++){
            float4 u1 = *(const float4*)(ue0 + (size_t)i*NH*HH + p);
            float4 u2 = *(const float4*)(un0 + (size_t)i*NH*HH + p);
            acc[i] += u1.x*w1.x + u1.y*w1.y + u1.z*w1.z + u1.w*w1.w
                    + u2.x*w2.x + u2.y*w2.y + u2.z*w2.z + u2.w*w2.w;
        }
    }
    float bsum = bv1[h*32+j] + bv2[h*32+j];
    #pragma unroll
    for (int i=0;i<8;i++){
        int nm = nm0 + ty*8 + i;
        float dn = g_dn[nm*NH + h];
        float asum = dn/(dn + 1e-16f);
        ego[(size_t)nm*256 + h*32 + j] += acc[i] + asum*bsum;
    }
}

// ---------------- driver ----------------
extern "C" void kernel_launch(void* const* d_in, const int* in_sizes, int n_in,
                              void* d_out, int out_size)
{
    const int*   batch = (const int*)d_in[0];
    const float* ego_f = (const float*)d_in[1];
    const float* ef    = (const float*)d_in[2];
    const float* nf    = (const float*)d_in[3];
    const float* Wk  = (const float*)d_in[4];
    const float* bk  = (const float*)d_in[5];
    const float* Wq  = (const float*)d_in[6];
    const float* bq  = (const float*)d_in[7];
    const float* Wv1 = (const float*)d_in[8];
    const float* bv1 = (const float*)d_in[9];
    const float* Wv2 = (const float*)d_in[10];
    const float* bv2 = (const float*)d_in[11];
    const float* ln1w= (const float*)d_in[12];
    const float* ln1b= (const float*)d_in[13];
    const float* ln2w= (const float*)d_in[14];
    const float* ln2b= (const float*)d_in[15];
    const float* W1  = (const float*)d_in[16];
    const float* b1  = (const float*)d_in[17];
    const float* W2  = (const float*)d_in[18];
    const float* b2  = (const float*)d_in[19];
    const float* Wd  = (const float*)d_in[20];
    const float* bd  = (const float*)d_in[21];
    float* ego = (float*)d_out;

    cudaMemcpyAsync(ego, ego_f, (size_t)NM*HID*sizeof(float),
                    cudaMemcpyDeviceToDevice, 0);
    rowstart_kernel<<<5, 256>>>(batch);
    foldln_kernel<<<dim3(4,2,3), 256>>>(Wq, bq, ln1w, ln1b, W1, b1, ln2w, ln2b);
    compose_kernel<<<dim3(4,4,3), 256>>>(Wd, W2);
    composebias_kernel<<<dim3(4,3), 256>>>(bd, W2, b2);

    dim3 ggemm(NM/64, HID/64);
    for (int l=0;l<3;l++){
        // --- attention block ---
        stats_kernel<<<NM/8, 256>>>(ego);
        gemm_kernel<<<ggemm, 128>>>(0, 0, l, ego, 0, 0);   // g_q = LN1(ego)@Wq' + bq'
        qkfold_kernel<<<dim3(NM/64, NH), 256>>>(Wk + (size_t)l*HH*HID, bk + l*HID);
        scores_kernel<<<dim3(NEGO, MM), 256>>>(ef);
        agg_kernel<<<dim3(NEGO, MM), 128>>>(ef, nf);
        vtrans_kernel<<<dim3(NM/64, NH), 256>>>(Wv1 + (size_t)l*HH*HID, bv1 + l*HID,
                                                Wv2 + (size_t)l*HH*HID, bv2 + l*HID, ego);
        // --- ff block (Wd@W2 composed) ---
        stats_kernel<<<NM/8, 256>>>(ego);
        gemm_kernel<<<ggemm, 128>>>(0, 1, l, ego, 1, 1);   // g_hmid = relu(LN2(ego)@W1' + b1')
        gemm_kernel<<<ggemm, 128>>>(1, 2, l, ego, 2, 0);   // ego += g_hmid@Wc + bc
    }
    (void)in_sizes; (void)n_in; (void)out_size;
}